// round 5
// baseline (speedup 1.0000x reference)
#include <cuda_runtime.h>
#include <cuda_bf16.h>
#include <math.h>
#include <stdint.h>

#define B_  64
#define T_  20
#define H_  512
#define E_  512
#define V_  32000
#define NN_ 8192
#define G4  2048   // 4*H
#define NB  148    // persistent grid (<= SM count, 1 wave resident)

// ---------------- static scratch (no allocations allowed) ----------------
__device__ float d_node_proj[NN_ * H_];
__device__ float d_embpart[T_ * B_ * G4];     // emb@Wih0_E^T + b_ih0+b_hh0 (ORIGINAL gate order)
__device__ float d_hist[B_ * T_ * H_];
__device__ float d_c0[B_ * H_];
__device__ float d_c1[B_ * H_];
__device__ float d_bs0[G4];
__device__ float d_bs1[G4];
__device__ int   d_gidx[T_ * B_];

// bf16 hi/lo split weights. W0p/W1p are PERMUTED: col = j*4+q <- orig row q*512+j
__device__ __nv_bfloat16 d_Wah[H_ * H_], d_Wal[H_ * H_];
__device__ __nv_bfloat16 d_W0h[G4 * 1024], d_W0l[G4 * 1024];
__device__ __nv_bfloat16 d_W1h[G4 * 1024], d_W1l[G4 * 1024];
__device__ __nv_bfloat16 d_xah[B_ * 1024], d_xal[B_ * 1024];  // [ctx | h0]
__device__ __nv_bfloat16 d_xbh[B_ * 1024], d_xbl[B_ * 1024];  // [h0n | h1]

// split-K partial buffers (deterministic, no atomics); gate partials in PERMUTED col order
__device__ float d_hppart[2 * B_ * H_];
__device__ float d_g0part[2 * B_ * G4];
__device__ float d_g1part[2 * B_ * G4];
__device__ unsigned g_cnt;   // global barrier counter (reset in prep)

// ===================== helpers =====================
__device__ __forceinline__ uint32_t smem_u32(const void* p) {
    uint32_t a;
    asm("{ .reg .u64 t; cvta.to.shared.u64 t, %1; cvt.u32.u64 %0, t; }"
        : "=r"(a) : "l"(p));
    return a;
}
__device__ __forceinline__ void ldsm4(uint32_t* r, uint32_t addr) {
    asm volatile("ldmatrix.sync.aligned.m8n8.x4.shared.b16 {%0,%1,%2,%3}, [%4];"
                 : "=r"(r[0]), "=r"(r[1]), "=r"(r[2]), "=r"(r[3]) : "r"(addr));
}
__device__ __forceinline__ void ldsm2(uint32_t* r, uint32_t addr) {
    asm volatile("ldmatrix.sync.aligned.m8n8.x2.shared.b16 {%0,%1}, [%2];"
                 : "=r"(r[0]), "=r"(r[1]) : "r"(addr));
}
__device__ __forceinline__ void mma_bf16(float* d, const uint32_t* a, const uint32_t* b) {
    asm volatile(
        "mma.sync.aligned.m16n8k16.row.col.f32.bf16.bf16.f32 "
        "{%0,%1,%2,%3}, {%4,%5,%6,%7}, {%8,%9}, {%0,%1,%2,%3};"
        : "+f"(d[0]), "+f"(d[1]), "+f"(d[2]), "+f"(d[3])
        : "r"(a[0]), "r"(a[1]), "r"(a[2]), "r"(a[3]), "r"(b[0]), "r"(b[1]));
}
__device__ __forceinline__ void split1(float v, __nv_bfloat16& h, __nv_bfloat16& l) {
    h = __float2bfloat16(v);
    l = __float2bfloat16(v - __bfloat162float(h));
}
__device__ __forceinline__ void split4(float4 a, uint2& hi, uint2& lo) {
    __nv_bfloat16 h0, h1, h2, h3, l0, l1, l2, l3;
    split1(a.x, h0, l0); split1(a.y, h1, l1);
    split1(a.z, h2, l2); split1(a.w, h3, l3);
    __nv_bfloat162 ph = __nv_bfloat162(h0, h1), qh = __nv_bfloat162(h2, h3);
    __nv_bfloat162 pl = __nv_bfloat162(l0, l1), ql = __nv_bfloat162(l2, l3);
    hi = make_uint2(*(uint32_t*)&ph, *(uint32_t*)&qh);
    lo = make_uint2(*(uint32_t*)&pl, *(uint32_t*)&ql);
}
__device__ __forceinline__ float sigf(float x) { return 1.f / (1.f + expf(-x)); }

// ========== big split-bf16 HMMA GEMM (validated in R3/R4) ================
#define TG_STAGE 40960
#define TG_SMEM  (2 * TG_STAGE)

__global__ void __launch_bounds__(256, 1) tgemm(
    const float* __restrict__ A, int lda,
    const float* __restrict__ Bw, int ldb,
    float* __restrict__ C, int ldc,
    const float* __restrict__ bias,
    int K, const int* __restrict__ gidx)
{
    extern __shared__ char sm[];
    const uint32_t sbase = smem_u32(sm);
    const int tid = threadIdx.x;
    const int lane = tid & 31, wid = tid >> 5;
    const int wm = wid & 1, wn = wid >> 1;
    const int m0 = blockIdx.x * 128, n0 = blockIdx.y * 128;
    const int lrow = tid >> 3;
    const int c4 = (tid & 7) << 2;
    const uint32_t aLane = (((uint32_t)(lane & 15) * 40u) + ((lane >> 4) * 8u)) * 2u;
    const uint32_t bLane = (((uint32_t)(lane & 7) * 40u) + (((lane >> 3) & 1) * 8u)) * 2u;

    float acc[4][4][4];
#pragma unroll
    for (int i = 0; i < 4; i++)
#pragma unroll
        for (int j = 0; j < 4; j++)
#pragma unroll
            for (int q = 0; q < 4; q++) acc[i][j][q] = 0.f;

    const int nch = K >> 5;
    float4 ga[4], gb[4];
#pragma unroll
    for (int v = 0; v < 4; v++) {
        int row = lrow + v * 32;
        int gr = gidx ? gidx[m0 + row] : (m0 + row);
        ga[v] = *(const float4*)(A + (size_t)gr * lda + c4);
        gb[v] = *(const float4*)(Bw + (size_t)(n0 + row) * ldb + c4);
    }
#pragma unroll
    for (int v = 0; v < 4; v++) {
        int row = lrow + v * 32;
        uint32_t off = ((uint32_t)row * 40u + (uint32_t)c4) * 2u;
        uint2 hi, lo;
        split4(ga[v], hi, lo);
        *(uint2*)(sm + off) = hi;
        *(uint2*)(sm + 10240 + off) = lo;
        split4(gb[v], hi, lo);
        *(uint2*)(sm + 20480 + off) = hi;
        *(uint2*)(sm + 30720 + off) = lo;
    }
    __syncthreads();

    for (int ich = 0; ich < nch; ich++) {
        const bool pf = (ich + 1 < nch);
        if (pf) {
            const int kb = (ich + 1) << 5;
#pragma unroll
            for (int v = 0; v < 4; v++) {
                int row = lrow + v * 32;
                int gr = gidx ? gidx[m0 + row] : (m0 + row);
                ga[v] = *(const float4*)(A + (size_t)gr * lda + kb + c4);
                gb[v] = *(const float4*)(Bw + (size_t)(n0 + row) * ldb + kb + c4);
            }
        }
        const uint32_t st = sbase + (uint32_t)(ich & 1) * TG_STAGE;
#pragma unroll
        for (int kk = 0; kk < 2; kk++) {
            uint32_t Ah[4][4], Al[4][4], Bh[4][2], Bl[4][2];
#pragma unroll
            for (int ma = 0; ma < 4; ma++) {
                uint32_t ad = st + (uint32_t)(wm * 64 + ma * 16) * 80u + aLane + kk * 32u;
                ldsm4(Ah[ma], ad);
                ldsm4(Al[ma], ad + 10240u);
            }
#pragma unroll
            for (int na = 0; na < 4; na++) {
                uint32_t bd = st + 20480u + (uint32_t)(wn * 32 + na * 8) * 80u + bLane + kk * 32u;
                ldsm2(Bh[na], bd);
                ldsm2(Bl[na], bd + 10240u);
            }
#pragma unroll
            for (int ma = 0; ma < 4; ma++)
#pragma unroll
                for (int na = 0; na < 4; na++) {
                    mma_bf16(acc[ma][na], Ah[ma], Bh[na]);
                    mma_bf16(acc[ma][na], Al[ma], Bh[na]);
                    mma_bf16(acc[ma][na], Ah[ma], Bl[na]);
                }
        }
        if (pf) {
            char* dstS = sm + ((ich + 1) & 1) * TG_STAGE;
#pragma unroll
            for (int v = 0; v < 4; v++) {
                int row = lrow + v * 32;
                uint32_t off = ((uint32_t)row * 40u + (uint32_t)c4) * 2u;
                uint2 hi, lo;
                split4(ga[v], hi, lo);
                *(uint2*)(dstS + off) = hi;
                *(uint2*)(dstS + 10240 + off) = lo;
                split4(gb[v], hi, lo);
                *(uint2*)(dstS + 20480 + off) = hi;
                *(uint2*)(dstS + 30720 + off) = lo;
            }
        }
        __syncthreads();
    }

    const int g = lane >> 2, t = lane & 3;
#pragma unroll
    for (int ma = 0; ma < 4; ma++) {
        int r = m0 + wm * 64 + ma * 16 + g;
#pragma unroll
        for (int na = 0; na < 4; na++) {
            int c = n0 + wn * 32 + na * 8 + 2 * t;
            float2 bb = make_float2(0.f, 0.f);
            if (bias) bb = *(const float2*)(bias + c);
            *(float2*)(C + (size_t)r * ldc + c) =
                make_float2(acc[ma][na][0] + bb.x, acc[ma][na][1] + bb.y);
            *(float2*)(C + (size_t)(r + 8) * ldc + c) =
                make_float2(acc[ma][na][2] + bb.x, acc[ma][na][3] + bb.y);
        }
    }
}

// ==================== persistent recurrence kernel =======================
struct AttnSh {
    float hp[512];
    float ctx[8][512];
    float m[8], s[8];
};
union RecSh {
    __nv_bfloat16 g[2 * 10240];   // two GEMM stages (max NT=64: 2x20480 B)
    AttnSh a;
};

__device__ __forceinline__ void gbar(unsigned& bar)
{
    bar += NB;
    __threadfence();
    __syncthreads();
    if (threadIdx.x == 0) {
        atomicAdd(&g_cnt, 1u);
        volatile unsigned* pc = &g_cnt;
        while (*pc < bar) { __nanosleep(32); }
    }
    __syncthreads();
}

// --- double-buffered 64xNT HMMA GEMM core; acc[2][NT/32][4] in registers ---
template<int NT>
__device__ __forceinline__ void gemm_db(
    const __nv_bfloat16* __restrict__ Agh, const __nv_bfloat16* __restrict__ Agl, int lda,
    int kbeg, int klen,
    const __nv_bfloat16* __restrict__ Bgh, const __nv_bfloat16* __restrict__ Bgl, int ldb,
    int n0, __nv_bfloat16* sms, float (&acc)[2][NT / 32][4])
{
    constexpr int NA = NT / 32;
    constexpr uint32_t STB = (128 + 2 * NT) * 80;   // stage bytes
    constexpr uint32_t oAl = 5120;
    constexpr uint32_t oBh = 10240;
    constexpr uint32_t oBB = (uint32_t)NT * 80;     // Bl offset from Bh
    const int tid = threadIdx.x, lane = tid & 31, wid = tid >> 5;
    const int wm = wid & 1, wn = wid >> 1;
    const int grow = tid >> 2, gcol = (tid & 3) << 3;
    const bool bl = (NT == 64) || (tid < 128);
    const uint32_t aLane = (uint32_t)(((lane & 15) * 40 + (lane >> 4) * 8) * 2);
    const uint32_t bLane = (uint32_t)(((lane & 7) * 40 + ((lane >> 3) & 1) * 8) * 2);
    char* sb = (char*)sms;
    const uint32_t ub = smem_u32(sms);

#pragma unroll
    for (int i = 0; i < 2; i++)
#pragma unroll
        for (int j = 0; j < NA; j++)
#pragma unroll
            for (int q = 0; q < 4; q++) acc[i][j][q] = 0.f;

    const int nch = klen >> 5;
    uint4 rah, ral, rbh, rbl;

    rah = __ldcg((const uint4*)(Agh + (size_t)grow * lda + kbeg + gcol));
    ral = __ldcg((const uint4*)(Agl + (size_t)grow * lda + kbeg + gcol));
    if (bl) {
        rbh = *(const uint4*)(Bgh + (size_t)(n0 + grow) * ldb + kbeg + gcol);
        rbl = *(const uint4*)(Bgl + (size_t)(n0 + grow) * ldb + kbeg + gcol);
    }
    {
        uint32_t so = (uint32_t)(grow * 40 + gcol) * 2;
        *(uint4*)(sb + so) = rah;
        *(uint4*)(sb + oAl + so) = ral;
        if (bl) { *(uint4*)(sb + oBh + so) = rbh; *(uint4*)(sb + oBh + oBB + so) = rbl; }
    }
    __syncthreads();

    for (int ich = 0; ich < nch; ich++) {
        const bool pf = (ich + 1 < nch);
        if (pf) {
            int kb = kbeg + ((ich + 1) << 5);
            rah = __ldcg((const uint4*)(Agh + (size_t)grow * lda + kb + gcol));
            ral = __ldcg((const uint4*)(Agl + (size_t)grow * lda + kb + gcol));
            if (bl) {
                rbh = *(const uint4*)(Bgh + (size_t)(n0 + grow) * ldb + kb + gcol);
                rbl = *(const uint4*)(Bgl + (size_t)(n0 + grow) * ldb + kb + gcol);
            }
        }
        const uint32_t stg = (uint32_t)(ich & 1) * STB;
#pragma unroll
        for (int kk = 0; kk < 2; kk++) {
            uint32_t Ahf[2][4], Alf[2][4], Bhf[NA][2], Blf[NA][2];
#pragma unroll
            for (int ma = 0; ma < 2; ma++) {
                uint32_t ro = stg + (uint32_t)(wm * 32 + ma * 16) * 80u + aLane + kk * 32u;
                ldsm4(Ahf[ma], ub + ro);
                ldsm4(Alf[ma], ub + oAl + ro);
            }
#pragma unroll
            for (int na = 0; na < NA; na++) {
                uint32_t co = stg + oBh + (uint32_t)(wn * NA * 8 + na * 8) * 80u + bLane + kk * 32u;
                ldsm2(Bhf[na], ub + co);
                ldsm2(Blf[na], ub + oBB + co);
            }
#pragma unroll
            for (int ma = 0; ma < 2; ma++)
#pragma unroll
                for (int na = 0; na < NA; na++) {
                    mma_bf16(acc[ma][na], Ahf[ma], Bhf[na]);
                    mma_bf16(acc[ma][na], Alf[ma], Bhf[na]);
                    mma_bf16(acc[ma][na], Ahf[ma], Blf[na]);
                }
        }
        if (pf) {
            uint32_t so = (uint32_t)(grow * 40 + gcol) * 2 + (uint32_t)((ich + 1) & 1) * STB;
            *(uint4*)(sb + so) = rah;
            *(uint4*)(sb + oAl + so) = ral;
            if (bl) { *(uint4*)(sb + oBh + so) = rbh; *(uint4*)(sb + oBh + oBB + so) = rbl; }
        }
        __syncthreads();
    }
}

__device__ __forceinline__ void write_part64(float (&acc)[2][2][4],
                                             float* __restrict__ Cp, int ldc, int n0)
{
    const int lane = threadIdx.x & 31, wid = threadIdx.x >> 5;
    const int wm = wid & 1, wn = wid >> 1;
    const int g = lane >> 2, qt = lane & 3;
#pragma unroll
    for (int ma = 0; ma < 2; ma++) {
        int r = wm * 32 + ma * 16 + g;
#pragma unroll
        for (int na = 0; na < 2; na++) {
            int c = n0 + wn * 16 + na * 8 + qt * 2;
            *(float2*)(Cp + (size_t)r * ldc + c) = make_float2(acc[ma][na][0], acc[ma][na][1]);
            *(float2*)(Cp + (size_t)(r + 8) * ldc + c) = make_float2(acc[ma][na][2], acc[ma][na][3]);
        }
    }
}

// fused gate-reduce + LSTM cell. Tile cols are PERMUTED: col = j*4+q.
template<int LAYER>
__device__ __forceinline__ void fused_cell(
    float (&acc)[2][1][4],
    const float* __restrict__ part0, const float* __restrict__ part1,
    int n0, int t)
{
    const int lane = threadIdx.x & 31, wid = threadIdx.x >> 5;
    const int wm = wid & 1, wn = wid >> 1;
    const int g = lane >> 2, qt = lane & 3;
    const int cA = n0 + wn * 8 + qt * 2;          // this thread's 2 perm cols: cA, cA+1
    const int j = (n0 >> 2) + wn * 2 + (qt >> 1); // hidden index for these cols
    const int qa = cA & 3, qb = (cA + 1) & 3;     // gate indices (0,1) or (2,3)

#pragma unroll
    for (int ma = 0; ma < 2; ma++) {
#pragma unroll
        for (int rr = 0; rr < 2; rr++) {
            const int b = wm * 32 + ma * 16 + g + rr * 8;
            float va = acc[ma][0][rr * 2 + 0];
            float vb = acc[ma][0][rr * 2 + 1];
            va += __ldcg(part0 + (size_t)b * G4 + cA) + __ldcg(part1 + (size_t)b * G4 + cA);
            vb += __ldcg(part0 + (size_t)b * G4 + cA + 1) + __ldcg(part1 + (size_t)b * G4 + cA + 1);
            if (LAYER == 0) {
                const float* ep = d_embpart + ((size_t)t * B_ + b) * G4;
                va += ep[qa * 512 + j];
                vb += ep[qb * 512 + j];
            } else {
                va += d_bs1[qa * 512 + j];
                vb += d_bs1[qb * 512 + j];
            }
            float oa = __shfl_xor_sync(0xffffffffu, va, 1);
            float ob = __shfl_xor_sync(0xffffffffu, vb, 1);
            if ((qt & 1) == 0) {
                // this lane: gates (0,1) = (va,vb); partner: gates (2,3) = (oa,ob)
                float gi = va, gf = vb, gg = oa, go = ob;
                if (LAYER == 0) {
                    float cc = sigf(gf) * d_c0[b * 512 + j] + sigf(gi) * tanhf(gg);
                    float h = sigf(go) * tanhf(cc);
                    d_c0[b * 512 + j] = cc;
                    __nv_bfloat16 hh, hl; split1(h, hh, hl);
                    d_xah[b * 1024 + 512 + j] = hh; d_xal[b * 1024 + 512 + j] = hl;
                    d_xbh[b * 1024 + j] = hh;       d_xbl[b * 1024 + j] = hl;
                } else {
                    float cc = sigf(gf) * d_c1[b * 512 + j] + sigf(gi) * tanhf(gg);
                    float h = sigf(go) * tanhf(cc);
                    d_c1[b * 512 + j] = cc;
                    __nv_bfloat16 hh, hl; split1(h, hh, hl);
                    d_xbh[b * 1024 + 512 + j] = hh; d_xbl[b * 1024 + 512 + j] = hl;
                    d_hist[((size_t)b * T_ + t) * H_ + j] = h;
                }
            }
        }
    }
}

__device__ __forceinline__ int lowbound(const int* __restrict__ a, int n, int v)
{
    int lo = 0, hi = n;
    while (lo < hi) { int mid = (lo + hi) >> 1; if (a[mid] < v) lo = mid + 1; else hi = mid; }
    return lo;
}

__device__ __forceinline__ void attn_phase(int b, const int* __restrict__ batch_idx,
                                           const float* __restrict__ b_a, AttnSh* s)
{
    const int tid = threadIdx.x, lane = tid & 31, w = tid >> 5;
    for (int j = tid; j < 512; j += 256) {
        float v = b_a[j]
                + __ldcg(d_hppart + b * 512 + j)
                + __ldcg(d_hppart + B_ * H_ + b * 512 + j);
        s->hp[j] = v;
    }
    __syncthreads();

    const int s0 = lowbound(batch_idx, NN_, b);
    const int s1 = lowbound(batch_idx, NN_, b + 1);

    float m = -INFINITY, ssum = 0.f;
    float ctx[16];
#pragma unroll
    for (int i = 0; i < 16; i++) ctx[i] = 0.f;

    for (int n = s0 + w; n < s1; n += 8) {
        const float* np = d_node_proj + (size_t)n * 512;
        float v[16]; float p = 0.f;
#pragma unroll
        for (int i = 0; i < 16; i++) {
            v[i] = np[lane + 32 * i];
            p = fmaf(v[i], s->hp[lane + 32 * i], p);
        }
#pragma unroll
        for (int o = 16; o > 0; o >>= 1) p += __shfl_xor_sync(0xffffffffu, p, o);
        float mn = fmaxf(m, p);
        float scale = expf(m - mn);
        float e = expf(p - mn);
        ssum = ssum * scale + e;
#pragma unroll
        for (int i = 0; i < 16; i++) ctx[i] = ctx[i] * scale + e * v[i];
        m = mn;
    }
#pragma unroll
    for (int i = 0; i < 16; i++) s->ctx[w][lane + 32 * i] = ctx[i];
    if (lane == 0) { s->m[w] = m; s->s[w] = ssum; }
    __syncthreads();

    float M = -INFINITY;
#pragma unroll
    for (int ww = 0; ww < 8; ww++) M = fmaxf(M, s->m[ww]);
    if (M == -INFINITY) {
        for (int jj = tid; jj < 512; jj += 256) {
            __nv_bfloat16 hh, hl; split1(0.f, hh, hl);
            d_xah[b * 1024 + jj] = hh; d_xal[b * 1024 + jj] = hl;
        }
    } else {
        float stot = 0.f;
        float ew[8];
#pragma unroll
        for (int ww = 0; ww < 8; ww++) { ew[ww] = expf(s->m[ww] - M); stot += s->s[ww] * ew[ww]; }
        float inv = 1.f / stot;
        for (int jj = tid; jj < 512; jj += 256) {
            float num = 0.f;
#pragma unroll
            for (int ww = 0; ww < 8; ww++) num = fmaf(s->ctx[ww][jj], ew[ww], num);
            float v = num * inv;
            __nv_bfloat16 hh, hl; split1(v, hh, hl);
            d_xah[b * 1024 + jj] = hh; d_xal[b * 1024 + jj] = hl;
        }
    }
}

__global__ __launch_bounds__(256) void recur_kernel(
    const int* __restrict__ batch_idx, const float* __restrict__ b_a)
{
    __shared__ __align__(16) RecSh sh;
    const int blk = blockIdx.x;
    unsigned bar = 0;
    float acc64[2][2][4];
    float acc32[2][1][4];

    for (int t = 0; t < T_; t++) {
        // P1: all (h0,h1)-dependent GEMM partials. 144 tasks.
        if (blk < 16) {
            int n0 = (blk & 7) * 64, kz = blk >> 3;
            gemm_db<64>(d_xbh + 512, d_xbl + 512, 1024, kz * 256, 256,
                        d_Wah, d_Wal, 512, n0, sh.g, acc64);
            write_part64(acc64, d_hppart + kz * B_ * H_, 512, n0);
        } else if (blk < 80) {
            int idx = blk - 16, n0 = (idx & 31) * 64, kz = idx >> 5;
            gemm_db<64>(d_xah, d_xal, 1024, 512 + kz * 256, 256,
                        d_W0h, d_W0l, 1024, n0, sh.g, acc64);
            write_part64(acc64, d_g0part + kz * B_ * G4, G4, n0);
        } else if (blk < 144) {
            int idx = blk - 80, n0 = (idx & 31) * 64, kz = idx >> 5;
            gemm_db<64>(d_xbh, d_xbl, 1024, 512 + kz * 256, 256,
                        d_W1h, d_W1l, 1024, n0, sh.g, acc64);
            write_part64(acc64, d_g1part + kz * B_ * G4, G4, n0);
        }
        gbar(bar);
        // P2: attention (hp reduce + segment online-softmax) -> ctx splits
        if (blk < 64) attn_phase(blk, batch_idx, b_a, &sh.a);
        gbar(bar);
        // P3: gates0 ctx-part (full K) + fused cell0
        if (blk < 64) {
            gemm_db<32>(d_xah, d_xal, 1024, 0, 512,
                        d_W0h, d_W0l, 1024, blk * 32, sh.g, acc32);
            fused_cell<0>(acc32, d_g0part, d_g0part + B_ * G4, blk * 32, t);
        }
        gbar(bar);
        // P4: gates1 h0n-part (full K) + fused cell1
        if (blk < 64) {
            gemm_db<32>(d_xbh, d_xbl, 1024, 0, 512,
                        d_W1h, d_W1l, 1024, blk * 32, sh.g, acc32);
            fused_cell<1>(acc32, d_g1part, d_g1part + B_ * G4, blk * 32, t);
        }
        gbar(bar);
    }
}

// ---------------- one-time prep ------------------------------------------
__global__ void prep_kernel(
    const float* __restrict__ gf,
    const float* __restrict__ W_a,
    const float* __restrict__ W_ih0, const float* __restrict__ W_hh0,
    const float* __restrict__ b_ih0, const float* __restrict__ b_hh0,
    const float* __restrict__ W_ih1, const float* __restrict__ W_hh1,
    const float* __restrict__ b_ih1, const float* __restrict__ b_hh1,
    const int* __restrict__ captions)
{
    int i = blockIdx.x * blockDim.x + threadIdx.x;
    if (i < G4 * 1024) {
        int col = i >> 10, k = i & 1023;
        int r = ((col & 3) << 9) + (col >> 2);   // orig gate row for permuted col
        float w0 = (k < 512) ? W_ih0[r * 1024 + 512 + k] : W_hh0[r * 512 + (k - 512)];
        float w1 = (k < 512) ? W_ih1[r * 512 + k] : W_hh1[r * 512 + (k - 512)];
        __nv_bfloat16 h, l;
        split1(w0, h, l); d_W0h[i] = h; d_W0l[i] = l;
        split1(w1, h, l); d_W1h[i] = h; d_W1l[i] = l;
    }
    if (i < H_ * H_) {
        __nv_bfloat16 h, l;
        split1(W_a[i], h, l); d_Wah[i] = h; d_Wal[i] = l;
    }
    if (i < G4) { d_bs0[i] = b_ih0[i] + b_hh0[i]; d_bs1[i] = b_ih1[i] + b_hh1[i]; }
    if (i < T_ * B_) { int t = i / 64, b = i % 64; d_gidx[i] = captions[b * T_ + t]; }
    if (i < B_ * H_) {
        int b = i >> 9, j = i & 511;
        __nv_bfloat16 h, l;
        split1(gf[i], h, l);
        d_xah[b * 1024 + 512 + j] = h; d_xal[b * 1024 + 512 + j] = l;  // h0
        d_xbh[b * 1024 + 512 + j] = h; d_xbl[b * 1024 + 512 + j] = l;  // h1
        d_c0[i] = 0.f;
        d_c1[i] = 0.f;
    }
    if (i == 0) g_cnt = 0u;
}

// ---------------- launch --------------------------------------------------
extern "C" void kernel_launch(void* const* d_in, const int* in_sizes, int n_in,
                              void* d_out, int out_size)
{
    const float* gf     = (const float*)d_in[0];
    const float* nf     = (const float*)d_in[1];
    const float* emb    = (const float*)d_in[2];
    const float* W_a    = (const float*)d_in[3];
    const float* b_a    = (const float*)d_in[4];
    const float* W_c    = (const float*)d_in[5];
    const float* b_c    = (const float*)d_in[6];
    const float* W_ih0  = (const float*)d_in[7];
    const float* W_hh0  = (const float*)d_in[8];
    const float* b_ih0  = (const float*)d_in[9];
    const float* b_hh0  = (const float*)d_in[10];
    const float* W_ih1  = (const float*)d_in[11];
    const float* W_hh1  = (const float*)d_in[12];
    const float* b_ih1  = (const float*)d_in[13];
    const float* b_hh1  = (const float*)d_in[14];
    const float* W_fc   = (const float*)d_in[15];
    const float* b_fc   = (const float*)d_in[16];
    const int* batch_idx = (const int*)d_in[17];
    const int* captions  = (const int*)d_in[18];
    float* out = (float*)d_out;

    float *node_proj, *embpart, *hist, *bs0;
    int* gidx;
    cudaGetSymbolAddress((void**)&node_proj, d_node_proj);
    cudaGetSymbolAddress((void**)&embpart,   d_embpart);
    cudaGetSymbolAddress((void**)&hist,      d_hist);
    cudaGetSymbolAddress((void**)&bs0,       d_bs0);
    cudaGetSymbolAddress((void**)&gidx,      d_gidx);

    cudaFuncSetAttribute(tgemm, cudaFuncAttributeMaxDynamicSharedMemorySize, TG_SMEM);

    // one-time prep: permuted weight splits, bias sums, gather indices, state init
    prep_kernel<<<8192, 256>>>(gf, W_a, W_ih0, W_hh0, b_ih0, b_hh0,
                               W_ih1, W_hh1, b_ih1, b_hh1, captions);

    // node_proj = node_features @ W_c^T + b_c         [8192, 512]
    tgemm<<<dim3(NN_ / 128, H_ / 128), 256, TG_SMEM>>>(
        nf, H_, W_c, H_, node_proj, H_, b_c, H_, nullptr);

    // embpart = emb[captions] @ W_ih0[:, :512]^T + (b_ih0+b_hh0)   [1280, 2048]
    tgemm<<<dim3(T_ * B_ / 128, G4 / 128), 256, TG_SMEM>>>(
        emb, E_, W_ih0, 1024, embpart, G4, bs0, E_, gidx);

    // full recurrence: ONE persistent kernel, 20 steps, 4 barriers/step
    recur_kernel<<<NB, 256>>>(batch_idx, b_a);

    // logits = hist @ W_fc^T + b_fc  -> directly into out[b][t][v]
    tgemm<<<dim3(B_ * T_ / 128, V_ / 128), 256, TG_SMEM>>>(
        hist, H_, W_fc, H_, out, V_, b_fc, H_, nullptr);
}

// round 6
// speedup vs baseline: 1.0819x; 1.0819x over previous
#include <cuda_runtime.h>
#include <cuda_bf16.h>
#include <math.h>
#include <stdint.h>

#define B_  64
#define T_  20
#define H_  512
#define E_  512
#define V_  32000
#define NN_ 8192
#define G4  2048   // 4*H
#define NB  148    // persistent grid (<= SM count, 1 wave resident)

// ---------------- static scratch (no allocations allowed) ----------------
__device__ float d_node_proj[NN_ * H_];
__device__ float d_embpart[T_ * B_ * G4];     // emb@Wih0_E^T + b_ih0+b_hh0
__device__ float d_hist[B_ * T_ * H_];
__device__ float d_c0[B_ * H_];
__device__ float d_c1[B_ * H_];
__device__ float d_bs0[G4];
__device__ float d_bs1[G4];
__device__ int   d_gidx[T_ * B_];

// bf16 hi/lo split weights (one-time) and activations (per-step)
__device__ __nv_bfloat16 d_Wah[H_ * H_], d_Wal[H_ * H_];
__device__ __nv_bfloat16 d_W0h[G4 * 1024], d_W0l[G4 * 1024];
__device__ __nv_bfloat16 d_W1h[G4 * 1024], d_W1l[G4 * 1024];
__device__ __nv_bfloat16 d_xah[B_ * 1024], d_xal[B_ * 1024];  // [ctx | h0]
__device__ __nv_bfloat16 d_xbh[B_ * 1024], d_xbl[B_ * 1024];  // [h0n | h1]

// split-K partial buffers (deterministic, no atomics)
__device__ float d_hppart[8 * B_ * H_];
__device__ float d_gpart0[4 * B_ * G4];
__device__ float d_gpart1[4 * B_ * G4];

// barrier state: distinct 128B-strided arrival slots + one release word
__device__ unsigned d_arr[NB * 32];
__device__ unsigned d_rel;

// ===================== helpers =====================
__device__ __forceinline__ uint32_t smem_u32(const void* p) {
    uint32_t a;
    asm("{ .reg .u64 t; cvta.to.shared.u64 t, %1; cvt.u32.u64 %0, t; }"
        : "=r"(a) : "l"(p));
    return a;
}
__device__ __forceinline__ void ldsm4(uint32_t* r, uint32_t addr) {
    asm volatile("ldmatrix.sync.aligned.m8n8.x4.shared.b16 {%0,%1,%2,%3}, [%4];"
                 : "=r"(r[0]), "=r"(r[1]), "=r"(r[2]), "=r"(r[3]) : "r"(addr));
}
__device__ __forceinline__ void ldsm2(uint32_t* r, uint32_t addr) {
    asm volatile("ldmatrix.sync.aligned.m8n8.x2.shared.b16 {%0,%1}, [%2];"
                 : "=r"(r[0]), "=r"(r[1]) : "r"(addr));
}
__device__ __forceinline__ void mma_bf16(float* d, const uint32_t* a, const uint32_t* b) {
    asm volatile(
        "mma.sync.aligned.m16n8k16.row.col.f32.bf16.bf16.f32 "
        "{%0,%1,%2,%3}, {%4,%5,%6,%7}, {%8,%9}, {%0,%1,%2,%3};"
        : "+f"(d[0]), "+f"(d[1]), "+f"(d[2]), "+f"(d[3])
        : "r"(a[0]), "r"(a[1]), "r"(a[2]), "r"(a[3]), "r"(b[0]), "r"(b[1]));
}
__device__ __forceinline__ void split1(float v, __nv_bfloat16& h, __nv_bfloat16& l) {
    h = __float2bfloat16(v);
    l = __float2bfloat16(v - __bfloat162float(h));
}
__device__ __forceinline__ void split4(float4 a, uint2& hi, uint2& lo) {
    __nv_bfloat16 h0, h1, h2, h3, l0, l1, l2, l3;
    split1(a.x, h0, l0); split1(a.y, h1, l1);
    split1(a.z, h2, l2); split1(a.w, h3, l3);
    __nv_bfloat162 ph = __nv_bfloat162(h0, h1), qh = __nv_bfloat162(h2, h3);
    __nv_bfloat162 pl = __nv_bfloat162(l0, l1), ql = __nv_bfloat162(l2, l3);
    hi = make_uint2(*(uint32_t*)&ph, *(uint32_t*)&qh);
    lo = make_uint2(*(uint32_t*)&pl, *(uint32_t*)&ql);
}
__device__ __forceinline__ float sigf(float x) { return 1.f / (1.f + expf(-x)); }

// ========== big split-bf16 HMMA GEMM (validated R3/R4) ===================
#define TG_STAGE 40960
#define TG_SMEM  (2 * TG_STAGE)

__global__ void __launch_bounds__(256, 1) tgemm(
    const float* __restrict__ A, int lda,
    const float* __restrict__ Bw, int ldb,
    float* __restrict__ C, int ldc,
    const float* __restrict__ bias,
    int K, const int* __restrict__ gidx)
{
    extern __shared__ char sm[];
    const uint32_t sbase = smem_u32(sm);
    const int tid = threadIdx.x;
    const int lane = tid & 31, wid = tid >> 5;
    const int wm = wid & 1, wn = wid >> 1;
    const int m0 = blockIdx.x * 128, n0 = blockIdx.y * 128;
    const int lrow = tid >> 3;
    const int c4 = (tid & 7) << 2;
    const uint32_t aLane = (((uint32_t)(lane & 15) * 40u) + ((lane >> 4) * 8u)) * 2u;
    const uint32_t bLane = (((uint32_t)(lane & 7) * 40u) + (((lane >> 3) & 1) * 8u)) * 2u;

    float acc[4][4][4];
#pragma unroll
    for (int i = 0; i < 4; i++)
#pragma unroll
        for (int j = 0; j < 4; j++)
#pragma unroll
            for (int q = 0; q < 4; q++) acc[i][j][q] = 0.f;

    const int nch = K >> 5;
    float4 ga[4], gb[4];
#pragma unroll
    for (int v = 0; v < 4; v++) {
        int row = lrow + v * 32;
        int gr = gidx ? gidx[m0 + row] : (m0 + row);
        ga[v] = *(const float4*)(A + (size_t)gr * lda + c4);
        gb[v] = *(const float4*)(Bw + (size_t)(n0 + row) * ldb + c4);
    }
#pragma unroll
    for (int v = 0; v < 4; v++) {
        int row = lrow + v * 32;
        uint32_t off = ((uint32_t)row * 40u + (uint32_t)c4) * 2u;
        uint2 hi, lo;
        split4(ga[v], hi, lo);
        *(uint2*)(sm + off) = hi;
        *(uint2*)(sm + 10240 + off) = lo;
        split4(gb[v], hi, lo);
        *(uint2*)(sm + 20480 + off) = hi;
        *(uint2*)(sm + 30720 + off) = lo;
    }
    __syncthreads();

    for (int ich = 0; ich < nch; ich++) {
        const bool pf = (ich + 1 < nch);
        if (pf) {
            const int kb = (ich + 1) << 5;
#pragma unroll
            for (int v = 0; v < 4; v++) {
                int row = lrow + v * 32;
                int gr = gidx ? gidx[m0 + row] : (m0 + row);
                ga[v] = *(const float4*)(A + (size_t)gr * lda + kb + c4);
                gb[v] = *(const float4*)(Bw + (size_t)(n0 + row) * ldb + kb + c4);
            }
        }
        const uint32_t st = sbase + (uint32_t)(ich & 1) * TG_STAGE;
#pragma unroll
        for (int kk = 0; kk < 2; kk++) {
            uint32_t Ah[4][4], Al[4][4], Bh[4][2], Bl[4][2];
#pragma unroll
            for (int ma = 0; ma < 4; ma++) {
                uint32_t ad = st + (uint32_t)(wm * 64 + ma * 16) * 80u + aLane + kk * 32u;
                ldsm4(Ah[ma], ad);
                ldsm4(Al[ma], ad + 10240u);
            }
#pragma unroll
            for (int na = 0; na < 4; na++) {
                uint32_t bd = st + 20480u + (uint32_t)(wn * 32 + na * 8) * 80u + bLane + kk * 32u;
                ldsm2(Bh[na], bd);
                ldsm2(Bl[na], bd + 10240u);
            }
#pragma unroll
            for (int ma = 0; ma < 4; ma++)
#pragma unroll
                for (int na = 0; na < 4; na++) {
                    mma_bf16(acc[ma][na], Ah[ma], Bh[na]);
                    mma_bf16(acc[ma][na], Al[ma], Bh[na]);
                    mma_bf16(acc[ma][na], Ah[ma], Bl[na]);
                }
        }
        if (pf) {
            char* dstS = sm + ((ich + 1) & 1) * TG_STAGE;
#pragma unroll
            for (int v = 0; v < 4; v++) {
                int row = lrow + v * 32;
                uint32_t off = ((uint32_t)row * 40u + (uint32_t)c4) * 2u;
                uint2 hi, lo;
                split4(ga[v], hi, lo);
                *(uint2*)(dstS + off) = hi;
                *(uint2*)(dstS + 10240 + off) = lo;
                split4(gb[v], hi, lo);
                *(uint2*)(dstS + 20480 + off) = hi;
                *(uint2*)(dstS + 30720 + off) = lo;
            }
        }
        __syncthreads();
    }

    const int g = lane >> 2, t = lane & 3;
#pragma unroll
    for (int ma = 0; ma < 4; ma++) {
        int r = m0 + wm * 64 + ma * 16 + g;
#pragma unroll
        for (int na = 0; na < 4; na++) {
            int c = n0 + wn * 32 + na * 8 + 2 * t;
            float2 bb = make_float2(0.f, 0.f);
            if (bias) bb = *(const float2*)(bias + c);
            *(float2*)(C + (size_t)r * ldc + c) =
                make_float2(acc[ma][na][0] + bb.x, acc[ma][na][1] + bb.y);
            *(float2*)(C + (size_t)(r + 8) * ldc + c) =
                make_float2(acc[ma][na][2] + bb.x, acc[ma][na][3] + bb.y);
        }
    }
}

// ==================== persistent recurrence kernel =======================
struct AttnSh {
    float hp[512];
    float ctx[8][512];
    float m[8], s[8];
};
union RecSh {
    __nv_bfloat16 g[2 * 4 * 64 * 40];   // 2 stages x (Ah|Al|Bh|Bl) 64x32 tiles
    AttnSh a;
};

// low-contention global barrier: distinct arrival slots + single release word
__device__ __forceinline__ void gbar(unsigned& ep)
{
    ep++;
    __syncthreads();
    __threadfence();
    const int tid = threadIdx.x;
    if (blockIdx.x == 0) {
        if (tid > 0 && tid < NB) {
            volatile unsigned* p = &d_arr[tid * 32];
            while (*p < ep) { __nanosleep(32); }
        }
        __syncthreads();
        __threadfence();
        if (tid == 0) *(volatile unsigned*)&d_rel = ep;
    } else {
        if (tid == 0) {
            *(volatile unsigned*)&d_arr[blockIdx.x * 32] = ep;
            volatile unsigned* p = &d_rel;
            while (*p < ep) { __nanosleep(32); }
        }
        __syncthreads();
    }
    __threadfence();
}

// 64x64 HMMA task, 2-stage smem double buffer, ONE sync per K-chunk.
// Cp[64, 64 cols at n0] = Ahl[64, kbeg:kbeg+klen] @ Bhl^T (3-pass split)
__device__ __forceinline__ void gemm64_hmma(
    const __nv_bfloat16* __restrict__ Agh, const __nv_bfloat16* __restrict__ Agl, int lda,
    int kbeg, int klen,
    const __nv_bfloat16* __restrict__ Bgh, const __nv_bfloat16* __restrict__ Bgl,
    int ldb, int n0,
    float* __restrict__ Cp, int ldc, __nv_bfloat16* sms)
{
    // stage layout: Ah(5120) Al(5120) Bh(5120) Bl(5120) = 20480 B per stage
    char* sb = (char*)sms;
    const uint32_t ub = smem_u32(sms);
    const int tid = threadIdx.x, lane = tid & 31, wid = tid >> 5;
    const int wm = wid & 1, wn = wid >> 1;
    const int grow = tid >> 2, gcol = (tid & 3) << 3;
    const uint32_t aLane = (uint32_t)(((lane & 15) * 40 + (lane >> 4) * 8) * 2);
    const uint32_t bLane = (uint32_t)(((lane & 7) * 40 + ((lane >> 3) & 1) * 8) * 2);

    float acc[2][2][4];
#pragma unroll
    for (int i = 0; i < 2; i++)
#pragma unroll
        for (int j = 0; j < 2; j++)
#pragma unroll
            for (int q = 0; q < 4; q++) acc[i][j][q] = 0.f;

    const int nch = klen >> 5;
    uint4 rah, ral, rbh, rbl;
    rah = __ldcg((const uint4*)(Agh + (size_t)grow * lda + kbeg + gcol));
    ral = __ldcg((const uint4*)(Agl + (size_t)grow * lda + kbeg + gcol));
    rbh = *(const uint4*)(Bgh + (size_t)(n0 + grow) * ldb + kbeg + gcol);
    rbl = *(const uint4*)(Bgl + (size_t)(n0 + grow) * ldb + kbeg + gcol);

    for (int ich = 0; ich < nch; ich++) {
        const uint32_t st = (uint32_t)(ich & 1) * 20480u;
        {
            uint32_t so = st + (uint32_t)(grow * 40 + gcol) * 2;
            *(uint4*)(sb + so) = rah;
            *(uint4*)(sb + 5120 + so) = ral;
            *(uint4*)(sb + 10240 + so) = rbh;
            *(uint4*)(sb + 15360 + so) = rbl;
        }
        __syncthreads();
        if (ich + 1 < nch) {
            int kb = kbeg + ((ich + 1) << 5);
            rah = __ldcg((const uint4*)(Agh + (size_t)grow * lda + kb + gcol));
            ral = __ldcg((const uint4*)(Agl + (size_t)grow * lda + kb + gcol));
            rbh = *(const uint4*)(Bgh + (size_t)(n0 + grow) * ldb + kb + gcol);
            rbl = *(const uint4*)(Bgl + (size_t)(n0 + grow) * ldb + kb + gcol);
        }
#pragma unroll
        for (int kk = 0; kk < 2; kk++) {
            uint32_t Ahf[2][4], Alf[2][4], Bhf[2][2], Blf[2][2];
#pragma unroll
            for (int ma = 0; ma < 2; ma++) {
                uint32_t ro = st + (uint32_t)(wm * 32 + ma * 16) * 80u + aLane + kk * 32u;
                ldsm4(Ahf[ma], ub + ro);
                ldsm4(Alf[ma], ub + 5120u + ro);
            }
#pragma unroll
            for (int na = 0; na < 2; na++) {
                uint32_t co = st + 10240u + (uint32_t)(wn * 16 + na * 8) * 80u + bLane + kk * 32u;
                ldsm2(Bhf[na], ub + co);
                ldsm2(Blf[na], ub + 5120u + co);
            }
#pragma unroll
            for (int ma = 0; ma < 2; ma++)
#pragma unroll
                for (int na = 0; na < 2; na++) {
                    mma_bf16(acc[ma][na], Ahf[ma], Bhf[na]);
                    mma_bf16(acc[ma][na], Alf[ma], Bhf[na]);
                    mma_bf16(acc[ma][na], Ahf[ma], Blf[na]);
                }
        }
    }
    __syncthreads();

    const int gq = lane >> 2, qt = lane & 3;
#pragma unroll
    for (int ma = 0; ma < 2; ma++) {
        int r = wm * 32 + ma * 16 + gq;
#pragma unroll
        for (int na = 0; na < 2; na++) {
            int c = n0 + wn * 16 + na * 8 + qt * 2;
            *(float2*)(Cp + (size_t)r * ldc + c) =
                make_float2(acc[ma][na][0], acc[ma][na][1]);
            *(float2*)(Cp + (size_t)(r + 8) * ldc + c) =
                make_float2(acc[ma][na][2], acc[ma][na][3]);
        }
    }
}

__device__ __forceinline__ int lowbound(const int* __restrict__ a, int n, int v)
{
    int lo = 0, hi = n;
    while (lo < hi) { int mid = (lo + hi) >> 1; if (a[mid] < v) lo = mid + 1; else hi = mid; }
    return lo;
}

__device__ __forceinline__ void attn_phase(int b, const int* __restrict__ batch_idx,
                                           const float* __restrict__ b_a, AttnSh* s)
{
    const int tid = threadIdx.x, lane = tid & 31, w = tid >> 5;
    for (int j = tid; j < 512; j += 256) {
        float v = b_a[j];
#pragma unroll
        for (int kz = 0; kz < 8; kz++)
            v += __ldcg(d_hppart + kz * B_ * H_ + b * 512 + j);
        s->hp[j] = v;
    }
    __syncthreads();

    const int s0 = lowbound(batch_idx, NN_, b);
    const int s1 = lowbound(batch_idx, NN_, b + 1);

    float m = -INFINITY, ssum = 0.f;
    float ctx[16];
#pragma unroll
    for (int i = 0; i < 16; i++) ctx[i] = 0.f;

    for (int n = s0 + w; n < s1; n += 8) {
        const float* np = d_node_proj + (size_t)n * 512;
        float v[16]; float p = 0.f;
#pragma unroll
        for (int i = 0; i < 16; i++) {
            v[i] = np[lane + 32 * i];
            p = fmaf(v[i], s->hp[lane + 32 * i], p);
        }
#pragma unroll
        for (int o = 16; o > 0; o >>= 1) p += __shfl_xor_sync(0xffffffffu, p, o);
        float mn = fmaxf(m, p);
        float scale = expf(m - mn);
        float e = expf(p - mn);
        ssum = ssum * scale + e;
#pragma unroll
        for (int i = 0; i < 16; i++) ctx[i] = ctx[i] * scale + e * v[i];
        m = mn;
    }
#pragma unroll
    for (int i = 0; i < 16; i++) s->ctx[w][lane + 32 * i] = ctx[i];
    if (lane == 0) { s->m[w] = m; s->s[w] = ssum; }
    __syncthreads();

    float M = -INFINITY;
#pragma unroll
    for (int ww = 0; ww < 8; ww++) M = fmaxf(M, s->m[ww]);
    if (M == -INFINITY) {
        for (int j = tid; j < 512; j += 256) {
            __nv_bfloat16 hh, hl; split1(0.f, hh, hl);
            d_xah[b * 1024 + j] = hh; d_xal[b * 1024 + j] = hl;
        }
    } else {
        float stot = 0.f;
        float ew[8];
#pragma unroll
        for (int ww = 0; ww < 8; ww++) { ew[ww] = expf(s->m[ww] - M); stot += s->s[ww] * ew[ww]; }
        float inv = 1.f / stot;
        for (int j = tid; j < 512; j += 256) {
            float num = 0.f;
#pragma unroll
            for (int ww = 0; ww < 8; ww++) num = fmaf(s->ctx[ww][j], ew[ww], num);
            float v = num * inv;
            __nv_bfloat16 hh, hl; split1(v, hh, hl);
            d_xah[b * 1024 + j] = hh; d_xal[b * 1024 + j] = hl;
        }
    }
}

__device__ __forceinline__ void cell0_phase(int i, int t)
{
    int b = i >> 9, j = i & 511;
    const float* ep = d_embpart + (size_t)t * B_ * G4 + b * G4 + j;
    float g[4];
#pragma unroll
    for (int q = 0; q < 4; q++) {
        float v = ep[q * 512];
#pragma unroll
        for (int kz = 0; kz < 4; kz++)
            v += __ldcg(d_gpart0 + kz * B_ * G4 + b * G4 + q * 512 + j);
        g[q] = v;
    }
    float c = sigf(g[1]) * d_c0[i] + sigf(g[0]) * tanhf(g[2]);
    float h = sigf(g[3]) * tanhf(c);
    d_c0[i] = c;
    __nv_bfloat16 hh, hl; split1(h, hh, hl);
    d_xah[b * 1024 + 512 + j] = hh; d_xal[b * 1024 + 512 + j] = hl;
    d_xbh[b * 1024 + j] = hh;       d_xbl[b * 1024 + j] = hl;
}

__device__ __forceinline__ void cell1_phase(int i, int t)
{
    int b = i >> 9, j = i & 511;
    float g[4];
#pragma unroll
    for (int q = 0; q < 4; q++) {
        float v = d_bs1[q * 512 + j];
#pragma unroll
        for (int kz = 0; kz < 4; kz++)
            v += __ldcg(d_gpart1 + kz * B_ * G4 + b * G4 + q * 512 + j);
        g[q] = v;
    }
    float c = sigf(g[1]) * d_c1[i] + sigf(g[0]) * tanhf(g[2]);
    float h = sigf(g[3]) * tanhf(c);
    d_c1[i] = c;
    __nv_bfloat16 hh, hl; split1(h, hh, hl);
    d_xbh[b * 1024 + 512 + j] = hh; d_xbl[b * 1024 + 512 + j] = hl;
    d_hist[((size_t)b * T_ + t) * H_ + j] = h;
}

__global__ __launch_bounds__(256) void recur_kernel(
    const int* __restrict__ batch_idx, const float* __restrict__ b_a)
{
    __shared__ __align__(16) RecSh sh;
    const int blk = blockIdx.x;
    const int tid = threadIdx.x;
    unsigned ep = 0;

    for (int t = 0; t < T_; t++) {
        // P1: hp partials: 64 tasks (8 n-tiles x 8 k-chunks of 64)
        if (blk < 64) {
            int n0 = (blk & 7) * 64, kz = blk >> 3;
            gemm64_hmma(d_xbh + 512, d_xbl + 512, 1024, kz * 64, 64,
                        d_Wah, d_Wal, 512, n0,
                        d_hppart + kz * B_ * H_, 512, sh.g);
        }
        gbar(ep);
        // P2: attention (adds b_a + hp partial reduce)
        if (blk < 64) attn_phase(blk, batch_idx, b_a, &sh.a);
        gbar(ep);
        // P3: gates0 partials: 128 tasks (32 n-tiles x 4 k-chunks of 256)
        if (blk < 128) {
            int n0 = (blk & 31) * 64, kz = blk >> 5;
            gemm64_hmma(d_xah, d_xal, 1024, kz * 256, 256,
                        d_W0h, d_W0l, 1024, n0,
                        d_gpart0 + kz * B_ * G4, G4, sh.g);
        }
        gbar(ep);
        // P4: cell0
        if (blk < 128) cell0_phase(blk * 256 + tid, t);
        gbar(ep);
        // P5: gates1 partials
        if (blk < 128) {
            int n0 = (blk & 31) * 64, kz = blk >> 5;
            gemm64_hmma(d_xbh, d_xbl, 1024, kz * 256, 256,
                        d_W1h, d_W1l, 1024, n0,
                        d_gpart1 + kz * B_ * G4, G4, sh.g);
        }
        gbar(ep);
        // P6: cell1
        if (blk < 128) cell1_phase(blk * 256 + tid, t);
        gbar(ep);
    }
}

// ---------------- one-time prep ------------------------------------------
__global__ void prep_kernel(
    const float* __restrict__ gf,
    const float* __restrict__ W_a,
    const float* __restrict__ W_ih0, const float* __restrict__ W_hh0,
    const float* __restrict__ b_ih0, const float* __restrict__ b_hh0,
    const float* __restrict__ W_ih1, const float* __restrict__ W_hh1,
    const float* __restrict__ b_ih1, const float* __restrict__ b_hh1,
    const int* __restrict__ captions)
{
    int i = blockIdx.x * blockDim.x + threadIdx.x;
    if (i < G4 * 1024) {
        int n = i >> 10, k = i & 1023;
        float w0 = (k < 512) ? W_ih0[n * 1024 + 512 + k] : W_hh0[n * 512 + (k - 512)];
        float w1 = (k < 512) ? W_ih1[n * 512 + k] : W_hh1[n * 512 + (k - 512)];
        __nv_bfloat16 h, l;
        split1(w0, h, l); d_W0h[i] = h; d_W0l[i] = l;
        split1(w1, h, l); d_W1h[i] = h; d_W1l[i] = l;
    }
    if (i < H_ * H_) {
        __nv_bfloat16 h, l;
        split1(W_a[i], h, l); d_Wah[i] = h; d_Wal[i] = l;
    }
    if (i < G4) { d_bs0[i] = b_ih0[i] + b_hh0[i]; d_bs1[i] = b_ih1[i] + b_hh1[i]; }
    if (i < T_ * B_) { int t = i / 64, b = i % 64; d_gidx[i] = captions[b * T_ + t]; }
    if (i < B_ * H_) {
        int b = i >> 9, j = i & 511;
        __nv_bfloat16 h, l;
        split1(gf[i], h, l);
        d_xah[b * 1024 + 512 + j] = h; d_xal[b * 1024 + 512 + j] = l;  // h0
        d_xbh[b * 1024 + 512 + j] = h; d_xbl[b * 1024 + 512 + j] = l;  // h1
        d_c0[i] = 0.f;
        d_c1[i] = 0.f;
    }
    if (i < NB * 32) d_arr[i] = 0u;
    if (i == 0) d_rel = 0u;
}

// ---------------- launch --------------------------------------------------
extern "C" void kernel_launch(void* const* d_in, const int* in_sizes, int n_in,
                              void* d_out, int out_size)
{
    const float* gf     = (const float*)d_in[0];
    const float* nf     = (const float*)d_in[1];
    const float* emb    = (const float*)d_in[2];
    const float* W_a    = (const float*)d_in[3];
    const float* b_a    = (const float*)d_in[4];
    const float* W_c    = (const float*)d_in[5];
    const float* b_c    = (const float*)d_in[6];
    const float* W_ih0  = (const float*)d_in[7];
    const float* W_hh0  = (const float*)d_in[8];
    const float* b_ih0  = (const float*)d_in[9];
    const float* b_hh0  = (const float*)d_in[10];
    const float* W_ih1  = (const float*)d_in[11];
    const float* W_hh1  = (const float*)d_in[12];
    const float* b_ih1  = (const float*)d_in[13];
    const float* b_hh1  = (const float*)d_in[14];
    const float* W_fc   = (const float*)d_in[15];
    const float* b_fc   = (const float*)d_in[16];
    const int* batch_idx = (const int*)d_in[17];
    const int* captions  = (const int*)d_in[18];
    float* out = (float*)d_out;

    float *node_proj, *embpart, *hist, *bs0;
    int* gidx;
    cudaGetSymbolAddress((void**)&node_proj, d_node_proj);
    cudaGetSymbolAddress((void**)&embpart,   d_embpart);
    cudaGetSymbolAddress((void**)&hist,      d_hist);
    cudaGetSymbolAddress((void**)&bs0,       d_bs0);
    cudaGetSymbolAddress((void**)&gidx,      d_gidx);

    cudaFuncSetAttribute(tgemm, cudaFuncAttributeMaxDynamicSharedMemorySize, TG_SMEM);

    // one-time prep: weight splits, bias sums, gather indices, state init
    prep_kernel<<<8192, 256>>>(gf, W_a, W_ih0, W_hh0, b_ih0, b_hh0,
                               W_ih1, W_hh1, b_ih1, b_hh1, captions);

    // node_proj = node_features @ W_c^T + b_c         [8192, 512]
    tgemm<<<dim3(NN_ / 128, H_ / 128), 256, TG_SMEM>>>(
        nf, H_, W_c, H_, node_proj, H_, b_c, H_, nullptr);

    // embpart = emb[captions] @ W_ih0[:, :512]^T + (b_ih0+b_hh0)   [1280, 2048]
    tgemm<<<dim3(T_ * B_ / 128, G4 / 128), 256, TG_SMEM>>>(
        emb, E_, W_ih0, 1024, embpart, G4, bs0, E_, gidx);

    // full recurrence: ONE persistent kernel, 20 steps, 6 barriers/step
    recur_kernel<<<NB, 256>>>(batch_idx, b_a);

    // logits = hist @ W_fc^T + b_fc  -> directly into out[b][t][v]
    tgemm<<<dim3(B_ * T_ / 128, V_ / 128), 256, TG_SMEM>>>(
        hist, H_, W_fc, H_, out, V_, b_fc, H_, nullptr);
}

// round 7
// speedup vs baseline: 1.2425x; 1.1484x over previous
#include <cuda_runtime.h>
#include <cuda_bf16.h>
#include <math.h>
#include <stdint.h>

#define B_  64
#define T_  20
#define H_  512
#define E_  512
#define V_  32000
#define NN_ 8192
#define G4  2048   // 4*H
#define NB  148    // persistent grid (<= SM count, 1 wave resident)

// ---------------- static scratch (no allocations allowed) ----------------
__device__ float d_node_proj[NN_ * H_];
__device__ float d_embpart[T_ * B_ * G4];     // emb@Wih0_E^T + b_ih0+b_hh0
__device__ float d_hist[B_ * T_ * H_];
__device__ float d_c0[B_ * H_];
__device__ float d_c1[B_ * H_];
__device__ float d_bs0[G4];
__device__ float d_bs1[G4];
__device__ int   d_gidx[T_ * B_];

// bf16 hi/lo split weights (one-time) and activations (per-step)
__device__ __nv_bfloat16 d_Wah[H_ * H_], d_Wal[H_ * H_];
__device__ __nv_bfloat16 d_W0h[G4 * 1024], d_W0l[G4 * 1024];
__device__ __nv_bfloat16 d_W1h[G4 * 1024], d_W1l[G4 * 1024];
__device__ __nv_bfloat16 d_xah[B_ * 1024], d_xal[B_ * 1024];  // [ctx | h0]
__device__ __nv_bfloat16 d_xbh[B_ * 1024], d_xbl[B_ * 1024];  // [h0n | h1]

// split-K partial buffers (deterministic, no atomics)
__device__ float d_hppart[8 * B_ * H_];
__device__ float d_gpart0[4 * B_ * G4];
__device__ float d_gpart1[4 * B_ * G4];
__device__ unsigned g_cnt;   // global barrier counter (reset in prep)

// ===================== helpers =====================
__device__ __forceinline__ uint32_t smem_u32(const void* p) {
    uint32_t a;
    asm("{ .reg .u64 t; cvta.to.shared.u64 t, %1; cvt.u32.u64 %0, t; }"
        : "=r"(a) : "l"(p));
    return a;
}
__device__ __forceinline__ void ldsm4(uint32_t* r, uint32_t addr) {
    asm volatile("ldmatrix.sync.aligned.m8n8.x4.shared.b16 {%0,%1,%2,%3}, [%4];"
                 : "=r"(r[0]), "=r"(r[1]), "=r"(r[2]), "=r"(r[3]) : "r"(addr));
}
__device__ __forceinline__ void ldsm2(uint32_t* r, uint32_t addr) {
    asm volatile("ldmatrix.sync.aligned.m8n8.x2.shared.b16 {%0,%1}, [%2];"
                 : "=r"(r[0]), "=r"(r[1]) : "r"(addr));
}
__device__ __forceinline__ void mma_bf16(float* d, const uint32_t* a, const uint32_t* b) {
    asm volatile(
        "mma.sync.aligned.m16n8k16.row.col.f32.bf16.bf16.f32 "
        "{%0,%1,%2,%3}, {%4,%5,%6,%7}, {%8,%9}, {%0,%1,%2,%3};"
        : "+f"(d[0]), "+f"(d[1]), "+f"(d[2]), "+f"(d[3])
        : "r"(a[0]), "r"(a[1]), "r"(a[2]), "r"(a[3]), "r"(b[0]), "r"(b[1]));
}
__device__ __forceinline__ void split1(float v, __nv_bfloat16& h, __nv_bfloat16& l) {
    h = __float2bfloat16(v);
    l = __float2bfloat16(v - __bfloat162float(h));
}
__device__ __forceinline__ void split4(float4 a, uint2& hi, uint2& lo) {
    __nv_bfloat16 h0, h1, h2, h3, l0, l1, l2, l3;
    split1(a.x, h0, l0); split1(a.y, h1, l1);
    split1(a.z, h2, l2); split1(a.w, h3, l3);
    __nv_bfloat162 ph = __nv_bfloat162(h0, h1), qh = __nv_bfloat162(h2, h3);
    __nv_bfloat162 pl = __nv_bfloat162(l0, l1), ql = __nv_bfloat162(l2, l3);
    hi = make_uint2(*(uint32_t*)&ph, *(uint32_t*)&qh);
    lo = make_uint2(*(uint32_t*)&pl, *(uint32_t*)&ql);
}
__device__ __forceinline__ float sigf(float x) { return 1.f / (1.f + expf(-x)); }

// ========== big split-bf16 HMMA GEMM (validated R3/R4) ===================
#define TG_STAGE 40960
#define TG_SMEM  (2 * TG_STAGE)

__global__ void __launch_bounds__(256, 1) tgemm(
    const float* __restrict__ A, int lda,
    const float* __restrict__ Bw, int ldb,
    float* __restrict__ C, int ldc,
    const float* __restrict__ bias,
    int K, const int* __restrict__ gidx)
{
    extern __shared__ char sm[];
    const uint32_t sbase = smem_u32(sm);
    const int tid = threadIdx.x;
    const int lane = tid & 31, wid = tid >> 5;
    const int wm = wid & 1, wn = wid >> 1;
    const int m0 = blockIdx.x * 128, n0 = blockIdx.y * 128;
    const int lrow = tid >> 3;
    const int c4 = (tid & 7) << 2;
    const uint32_t aLane = (((uint32_t)(lane & 15) * 40u) + ((lane >> 4) * 8u)) * 2u;
    const uint32_t bLane = (((uint32_t)(lane & 7) * 40u) + (((lane >> 3) & 1) * 8u)) * 2u;

    float acc[4][4][4];
#pragma unroll
    for (int i = 0; i < 4; i++)
#pragma unroll
        for (int j = 0; j < 4; j++)
#pragma unroll
            for (int q = 0; q < 4; q++) acc[i][j][q] = 0.f;

    const int nch = K >> 5;
    float4 ga[4], gb[4];
#pragma unroll
    for (int v = 0; v < 4; v++) {
        int row = lrow + v * 32;
        int gr = gidx ? gidx[m0 + row] : (m0 + row);
        ga[v] = *(const float4*)(A + (size_t)gr * lda + c4);
        gb[v] = *(const float4*)(Bw + (size_t)(n0 + row) * ldb + c4);
    }
#pragma unroll
    for (int v = 0; v < 4; v++) {
        int row = lrow + v * 32;
        uint32_t off = ((uint32_t)row * 40u + (uint32_t)c4) * 2u;
        uint2 hi, lo;
        split4(ga[v], hi, lo);
        *(uint2*)(sm + off) = hi;
        *(uint2*)(sm + 10240 + off) = lo;
        split4(gb[v], hi, lo);
        *(uint2*)(sm + 20480 + off) = hi;
        *(uint2*)(sm + 30720 + off) = lo;
    }
    __syncthreads();

    for (int ich = 0; ich < nch; ich++) {
        const bool pf = (ich + 1 < nch);
        if (pf) {
            const int kb = (ich + 1) << 5;
#pragma unroll
            for (int v = 0; v < 4; v++) {
                int row = lrow + v * 32;
                int gr = gidx ? gidx[m0 + row] : (m0 + row);
                ga[v] = *(const float4*)(A + (size_t)gr * lda + kb + c4);
                gb[v] = *(const float4*)(Bw + (size_t)(n0 + row) * ldb + kb + c4);
            }
        }
        const uint32_t st = sbase + (uint32_t)(ich & 1) * TG_STAGE;
#pragma unroll
        for (int kk = 0; kk < 2; kk++) {
            uint32_t Ah[4][4], Al[4][4], Bh[4][2], Bl[4][2];
#pragma unroll
            for (int ma = 0; ma < 4; ma++) {
                uint32_t ad = st + (uint32_t)(wm * 64 + ma * 16) * 80u + aLane + kk * 32u;
                ldsm4(Ah[ma], ad);
                ldsm4(Al[ma], ad + 10240u);
            }
#pragma unroll
            for (int na = 0; na < 4; na++) {
                uint32_t bd = st + 20480u + (uint32_t)(wn * 32 + na * 8) * 80u + bLane + kk * 32u;
                ldsm2(Bh[na], bd);
                ldsm2(Bl[na], bd + 10240u);
            }
#pragma unroll
            for (int ma = 0; ma < 4; ma++)
#pragma unroll
                for (int na = 0; na < 4; na++) {
                    mma_bf16(acc[ma][na], Ah[ma], Bh[na]);
                    mma_bf16(acc[ma][na], Al[ma], Bh[na]);
                    mma_bf16(acc[ma][na], Ah[ma], Bl[na]);
                }
        }
        if (pf) {
            char* dstS = sm + ((ich + 1) & 1) * TG_STAGE;
#pragma unroll
            for (int v = 0; v < 4; v++) {
                int row = lrow + v * 32;
                uint32_t off = ((uint32_t)row * 40u + (uint32_t)c4) * 2u;
                uint2 hi, lo;
                split4(ga[v], hi, lo);
                *(uint2*)(dstS + off) = hi;
                *(uint2*)(dstS + 10240 + off) = lo;
                split4(gb[v], hi, lo);
                *(uint2*)(dstS + 20480 + off) = hi;
                *(uint2*)(dstS + 30720 + off) = lo;
            }
        }
        __syncthreads();
    }

    const int g = lane >> 2, t = lane & 3;
#pragma unroll
    for (int ma = 0; ma < 4; ma++) {
        int r = m0 + wm * 64 + ma * 16 + g;
#pragma unroll
        for (int na = 0; na < 4; na++) {
            int c = n0 + wn * 32 + na * 8 + 2 * t;
            float2 bb = make_float2(0.f, 0.f);
            if (bias) bb = *(const float2*)(bias + c);
            *(float2*)(C + (size_t)r * ldc + c) =
                make_float2(acc[ma][na][0] + bb.x, acc[ma][na][1] + bb.y);
            *(float2*)(C + (size_t)(r + 8) * ldc + c) =
                make_float2(acc[ma][na][2] + bb.x, acc[ma][na][3] + bb.y);
        }
    }
}

// ==================== persistent recurrence kernel =======================
struct AttnSh {
    float hp[512];
    float ctx[8][512];
    float m[8], s[8];
};
// dynamic smem: max(2 gemm stages = 73728 B, AttnSh)
#define RC_STAGE 36864u     // Ah(9216) Al(9216) Bh(9216) Bl(9216), stride 144B
#define RC_SMEM  (2 * 36864)

// R4-proven global barrier: single atomic counter + broadcast poll
__device__ __forceinline__ void gbar(unsigned& bar)
{
    bar += NB;
    __threadfence();
    __syncthreads();
    if (threadIdx.x == 0) {
        atomicAdd(&g_cnt, 1u);
        volatile unsigned* pc = &g_cnt;
        while (*pc < bar) { __nanosleep(64); }
    }
    __syncthreads();
}

// 64x64 HMMA task, BK=64, 2-stage double buffer, ONE sync per chunk.
// Cp[64, 64 cols at n0] = Ahl[64, kbeg:kbeg+klen] @ Bhl^T (3-pass split)
__device__ __forceinline__ void gemm64_hmma(
    const __nv_bfloat16* __restrict__ Agh, const __nv_bfloat16* __restrict__ Agl, int lda,
    int kbeg, int klen,
    const __nv_bfloat16* __restrict__ Bgh, const __nv_bfloat16* __restrict__ Bgl,
    int ldb, int n0,
    float* __restrict__ Cp, int ldc, char* sb)
{
    const uint32_t ub = smem_u32(sb);
    const int tid = threadIdx.x, lane = tid & 31, wid = tid >> 5;
    const int wm = wid & 1, wn = wid >> 1;
    const int grow = tid >> 2;               // 0..63
    const int gc0 = (tid & 3) << 3;          // cols gc0 and gc0+32 (8 bf16 each)
    const uint32_t aLane = (uint32_t)((lane & 15) * 144 + (lane >> 4) * 16);
    const uint32_t bLane = (uint32_t)((lane & 7) * 144 + ((lane >> 3) & 1) * 16);

    float acc[2][2][4];
#pragma unroll
    for (int i = 0; i < 2; i++)
#pragma unroll
        for (int j = 0; j < 2; j++)
#pragma unroll
            for (int q = 0; q < 4; q++) acc[i][j][q] = 0.f;

    const int nch = klen >> 6;
    uint4 rah0, rah1, ral0, ral1, rbh0, rbh1, rbl0, rbl1;

#define RC_LOAD(kb)                                                              \
    do {                                                                         \
        const __nv_bfloat16* ap = Agh + (size_t)grow * lda + (kb) + gc0;         \
        const __nv_bfloat16* alp = Agl + (size_t)grow * lda + (kb) + gc0;        \
        const __nv_bfloat16* bp = Bgh + (size_t)(n0 + grow) * ldb + (kb) + gc0;  \
        const __nv_bfloat16* blp = Bgl + (size_t)(n0 + grow) * ldb + (kb) + gc0; \
        rah0 = __ldcg((const uint4*)ap);  rah1 = __ldcg((const uint4*)(ap + 32));  \
        ral0 = __ldcg((const uint4*)alp); ral1 = __ldcg((const uint4*)(alp + 32)); \
        rbh0 = *(const uint4*)bp;         rbh1 = *(const uint4*)(bp + 32);       \
        rbl0 = *(const uint4*)blp;        rbl1 = *(const uint4*)(blp + 32);      \
    } while (0)

#define RC_STORE(stg)                                                            \
    do {                                                                         \
        uint32_t so = (stg) + (uint32_t)(grow * 144 + gc0 * 2);                  \
        *(uint4*)(sb + so) = rah0;          *(uint4*)(sb + so + 64) = rah1;      \
        *(uint4*)(sb + 9216 + so) = ral0;   *(uint4*)(sb + 9216 + so + 64) = ral1; \
        *(uint4*)(sb + 18432 + so) = rbh0;  *(uint4*)(sb + 18432 + so + 64) = rbh1; \
        *(uint4*)(sb + 27648 + so) = rbl0;  *(uint4*)(sb + 27648 + so + 64) = rbl1; \
    } while (0)

    RC_LOAD(kbeg);
    RC_STORE(0u);
    __syncthreads();

    for (int ich = 0; ich < nch; ich++) {
        const bool pf = (ich + 1 < nch);
        if (pf) RC_LOAD(kbeg + ((ich + 1) << 6));
        const uint32_t st = (uint32_t)(ich & 1) * RC_STAGE;
#pragma unroll
        for (int kk = 0; kk < 4; kk++) {
            uint32_t Ahf[2][4], Alf[2][4], Bhf[2][2], Blf[2][2];
#pragma unroll
            for (int ma = 0; ma < 2; ma++) {
                uint32_t ro = st + (uint32_t)(wm * 32 + ma * 16) * 144u + aLane + kk * 32u;
                ldsm4(Ahf[ma], ub + ro);
                ldsm4(Alf[ma], ub + 9216u + ro);
            }
#pragma unroll
            for (int na = 0; na < 2; na++) {
                uint32_t co = st + 18432u + (uint32_t)(wn * 16 + na * 8) * 144u + bLane + kk * 32u;
                ldsm2(Bhf[na], ub + co);
                ldsm2(Blf[na], ub + 9216u + co);
            }
#pragma unroll
            for (int ma = 0; ma < 2; ma++)
#pragma unroll
                for (int na = 0; na < 2; na++) {
                    mma_bf16(acc[ma][na], Ahf[ma], Bhf[na]);
                    mma_bf16(acc[ma][na], Alf[ma], Bhf[na]);
                    mma_bf16(acc[ma][na], Ahf[ma], Blf[na]);
                }
        }
        if (pf) RC_STORE((uint32_t)((ich + 1) & 1) * RC_STAGE);
        __syncthreads();
    }
#undef RC_LOAD
#undef RC_STORE

    const int gq = lane >> 2, qt = lane & 3;
#pragma unroll
    for (int ma = 0; ma < 2; ma++) {
        int r = wm * 32 + ma * 16 + gq;
#pragma unroll
        for (int na = 0; na < 2; na++) {
            int c = n0 + wn * 16 + na * 8 + qt * 2;
            *(float2*)(Cp + (size_t)r * ldc + c) =
                make_float2(acc[ma][na][0], acc[ma][na][1]);
            *(float2*)(Cp + (size_t)(r + 8) * ldc + c) =
                make_float2(acc[ma][na][2], acc[ma][na][3]);
        }
    }
}

__device__ __forceinline__ int lowbound(const int* __restrict__ a, int n, int v)
{
    int lo = 0, hi = n;
    while (lo < hi) { int mid = (lo + hi) >> 1; if (a[mid] < v) lo = mid + 1; else hi = mid; }
    return lo;
}

// attention: lane owns contiguous cols lane*16..lane*16+15 (4x LDG.128/node)
__device__ __forceinline__ void attn_phase(int b, const int* __restrict__ batch_idx,
                                           const float* __restrict__ b_a, AttnSh* s)
{
    const int tid = threadIdx.x, lane = tid & 31, w = tid >> 5;
    for (int j = tid; j < 512; j += 256) {
        float v = b_a[j];
#pragma unroll
        for (int kz = 0; kz < 8; kz++)
            v += __ldcg(d_hppart + kz * B_ * H_ + b * 512 + j);
        s->hp[j] = v;
    }
    __syncthreads();

    float hpreg[16];
#pragma unroll
    for (int i = 0; i < 4; i++) {
        float4 t4 = *(const float4*)&s->hp[lane * 16 + i * 4];
        hpreg[i * 4 + 0] = t4.x; hpreg[i * 4 + 1] = t4.y;
        hpreg[i * 4 + 2] = t4.z; hpreg[i * 4 + 3] = t4.w;
    }

    const int s0 = lowbound(batch_idx, NN_, b);
    const int s1 = lowbound(batch_idx, NN_, b + 1);

    float m = -INFINITY, ssum = 0.f;
    float ctx[16];
#pragma unroll
    for (int i = 0; i < 16; i++) ctx[i] = 0.f;

#pragma unroll 2
    for (int n = s0 + w; n < s1; n += 8) {
        const float4* np = (const float4*)(d_node_proj + (size_t)n * 512 + lane * 16);
        float4 a0 = np[0], a1 = np[1], a2 = np[2], a3 = np[3];
        float v[16] = {a0.x, a0.y, a0.z, a0.w, a1.x, a1.y, a1.z, a1.w,
                       a2.x, a2.y, a2.z, a2.w, a3.x, a3.y, a3.z, a3.w};
        float p = 0.f;
#pragma unroll
        for (int i = 0; i < 16; i++) p = fmaf(v[i], hpreg[i], p);
#pragma unroll
        for (int o = 16; o > 0; o >>= 1) p += __shfl_xor_sync(0xffffffffu, p, o);
        float mn = fmaxf(m, p);
        float scale = expf(m - mn);
        float e = expf(p - mn);
        ssum = ssum * scale + e;
#pragma unroll
        for (int i = 0; i < 16; i++) ctx[i] = ctx[i] * scale + e * v[i];
        m = mn;
    }
#pragma unroll
    for (int i = 0; i < 4; i++)
        *(float4*)&s->ctx[w][lane * 16 + i * 4] =
            make_float4(ctx[i * 4], ctx[i * 4 + 1], ctx[i * 4 + 2], ctx[i * 4 + 3]);
    if (lane == 0) { s->m[w] = m; s->s[w] = ssum; }
    __syncthreads();

    float M = -INFINITY;
#pragma unroll
    for (int ww = 0; ww < 8; ww++) M = fmaxf(M, s->m[ww]);
    if (M == -INFINITY) {
        for (int j = tid; j < 512; j += 256) {
            __nv_bfloat16 hh, hl; split1(0.f, hh, hl);
            d_xah[b * 1024 + j] = hh; d_xal[b * 1024 + j] = hl;
        }
    } else {
        float stot = 0.f;
        float ew[8];
#pragma unroll
        for (int ww = 0; ww < 8; ww++) { ew[ww] = expf(s->m[ww] - M); stot += s->s[ww] * ew[ww]; }
        float inv = 1.f / stot;
        for (int j = tid; j < 512; j += 256) {
            float num = 0.f;
#pragma unroll
            for (int ww = 0; ww < 8; ww++) num = fmaf(s->ctx[ww][j], ew[ww], num);
            float v = num * inv;
            __nv_bfloat16 hh, hl; split1(v, hh, hl);
            d_xah[b * 1024 + j] = hh; d_xal[b * 1024 + j] = hl;
        }
    }
}

__device__ __forceinline__ void cell0_phase(int i, int t)
{
    int b = i >> 9, j = i & 511;
    const float* ep = d_embpart + (size_t)t * B_ * G4 + b * G4 + j;
    float g[4];
#pragma unroll
    for (int q = 0; q < 4; q++) {
        float v = ep[q * 512];
#pragma unroll
        for (int kz = 0; kz < 4; kz++)
            v += __ldcg(d_gpart0 + kz * B_ * G4 + b * G4 + q * 512 + j);
        g[q] = v;
    }
    float c = sigf(g[1]) * d_c0[i] + sigf(g[0]) * tanhf(g[2]);
    float h = sigf(g[3]) * tanhf(c);
    d_c0[i] = c;
    __nv_bfloat16 hh, hl; split1(h, hh, hl);
    d_xah[b * 1024 + 512 + j] = hh; d_xal[b * 1024 + 512 + j] = hl;
    d_xbh[b * 1024 + j] = hh;       d_xbl[b * 1024 + j] = hl;
}

__device__ __forceinline__ void cell1_phase(int i, int t)
{
    int b = i >> 9, j = i & 511;
    float g[4];
#pragma unroll
    for (int q = 0; q < 4; q++) {
        float v = d_bs1[q * 512 + j];
#pragma unroll
        for (int kz = 0; kz < 4; kz++)
            v += __ldcg(d_gpart1 + kz * B_ * G4 + b * G4 + q * 512 + j);
        g[q] = v;
    }
    float c = sigf(g[1]) * d_c1[i] + sigf(g[0]) * tanhf(g[2]);
    float h = sigf(g[3]) * tanhf(c);
    d_c1[i] = c;
    __nv_bfloat16 hh, hl; split1(h, hh, hl);
    d_xbh[b * 1024 + 512 + j] = hh; d_xbl[b * 1024 + 512 + j] = hl;
    d_hist[((size_t)b * T_ + t) * H_ + j] = h;
}

__global__ __launch_bounds__(256) void recur_kernel(
    const int* __restrict__ batch_idx, const float* __restrict__ b_a)
{
    extern __shared__ __align__(16) char dsm[];
    const int blk = blockIdx.x;
    const int tid = threadIdx.x;
    unsigned bar = 0;

    for (int t = 0; t < T_; t++) {
        // P1: hp partials: 64 tasks (8 n-tiles x 8 k-chunks of 64)
        if (blk < 64) {
            int n0 = (blk & 7) * 64, kz = blk >> 3;
            gemm64_hmma(d_xbh + 512, d_xbl + 512, 1024, kz * 64, 64,
                        d_Wah, d_Wal, 512, n0,
                        d_hppart + kz * B_ * H_, 512, dsm);
        }
        gbar(bar);
        // P2: attention (adds b_a + hp partial reduce)
        if (blk < 64) attn_phase(blk, batch_idx, b_a, (AttnSh*)dsm);
        gbar(bar);
        // P3: gates0 partials: 128 tasks (32 n-tiles x 4 k-chunks of 256)
        if (blk < 128) {
            int n0 = (blk & 31) * 64, kz = blk >> 5;
            gemm64_hmma(d_xah, d_xal, 1024, kz * 256, 256,
                        d_W0h, d_W0l, 1024, n0,
                        d_gpart0 + kz * B_ * G4, G4, dsm);
        }
        gbar(bar);
        // P4: cell0
        if (blk < 128) cell0_phase(blk * 256 + tid, t);
        gbar(bar);
        // P5: gates1 partials
        if (blk < 128) {
            int n0 = (blk & 31) * 64, kz = blk >> 5;
            gemm64_hmma(d_xbh, d_xbl, 1024, kz * 256, 256,
                        d_W1h, d_W1l, 1024, n0,
                        d_gpart1 + kz * B_ * G4, G4, dsm);
        }
        gbar(bar);
        // P6: cell1
        if (blk < 128) cell1_phase(blk * 256 + tid, t);
        gbar(bar);
    }
}

// ---------------- one-time prep ------------------------------------------
__global__ void prep_kernel(
    const float* __restrict__ gf,
    const float* __restrict__ W_a,
    const float* __restrict__ W_ih0, const float* __restrict__ W_hh0,
    const float* __restrict__ b_ih0, const float* __restrict__ b_hh0,
    const float* __restrict__ W_ih1, const float* __restrict__ W_hh1,
    const float* __restrict__ b_ih1, const float* __restrict__ b_hh1,
    const int* __restrict__ captions)
{
    int i = blockIdx.x * blockDim.x + threadIdx.x;
    if (i < G4 * 1024) {
        int n = i >> 10, k = i & 1023;
        float w0 = (k < 512) ? W_ih0[n * 1024 + 512 + k] : W_hh0[n * 512 + (k - 512)];
        float w1 = (k < 512) ? W_ih1[n * 512 + k] : W_hh1[n * 512 + (k - 512)];
        __nv_bfloat16 h, l;
        split1(w0, h, l); d_W0h[i] = h; d_W0l[i] = l;
        split1(w1, h, l); d_W1h[i] = h; d_W1l[i] = l;
    }
    if (i < H_ * H_) {
        __nv_bfloat16 h, l;
        split1(W_a[i], h, l); d_Wah[i] = h; d_Wal[i] = l;
    }
    if (i < G4) { d_bs0[i] = b_ih0[i] + b_hh0[i]; d_bs1[i] = b_ih1[i] + b_hh1[i]; }
    if (i < T_ * B_) { int t = i / 64, b = i % 64; d_gidx[i] = captions[b * T_ + t]; }
    if (i < B_ * H_) {
        int b = i >> 9, j = i & 511;
        __nv_bfloat16 h, l;
        split1(gf[i], h, l);
        d_xah[b * 1024 + 512 + j] = h; d_xal[b * 1024 + 512 + j] = l;  // h0
        d_xbh[b * 1024 + 512 + j] = h; d_xbl[b * 1024 + 512 + j] = l;  // h1
        d_c0[i] = 0.f;
        d_c1[i] = 0.f;
    }
    if (i == 0) g_cnt = 0u;
}

// ---------------- launch --------------------------------------------------
extern "C" void kernel_launch(void* const* d_in, const int* in_sizes, int n_in,
                              void* d_out, int out_size)
{
    const float* gf     = (const float*)d_in[0];
    const float* nf     = (const float*)d_in[1];
    const float* emb    = (const float*)d_in[2];
    const float* W_a    = (const float*)d_in[3];
    const float* b_a    = (const float*)d_in[4];
    const float* W_c    = (const float*)d_in[5];
    const float* b_c    = (const float*)d_in[6];
    const float* W_ih0  = (const float*)d_in[7];
    const float* W_hh0  = (const float*)d_in[8];
    const float* b_ih0  = (const float*)d_in[9];
    const float* b_hh0  = (const float*)d_in[10];
    const float* W_ih1  = (const float*)d_in[11];
    const float* W_hh1  = (const float*)d_in[12];
    const float* b_ih1  = (const float*)d_in[13];
    const float* b_hh1  = (const float*)d_in[14];
    const float* W_fc   = (const float*)d_in[15];
    const float* b_fc   = (const float*)d_in[16];
    const int* batch_idx = (const int*)d_in[17];
    const int* captions  = (const int*)d_in[18];
    float* out = (float*)d_out;

    float *node_proj, *embpart, *hist, *bs0;
    int* gidx;
    cudaGetSymbolAddress((void**)&node_proj, d_node_proj);
    cudaGetSymbolAddress((void**)&embpart,   d_embpart);
    cudaGetSymbolAddress((void**)&hist,      d_hist);
    cudaGetSymbolAddress((void**)&bs0,       d_bs0);
    cudaGetSymbolAddress((void**)&gidx,      d_gidx);

    cudaFuncSetAttribute(tgemm, cudaFuncAttributeMaxDynamicSharedMemorySize, TG_SMEM);
    cudaFuncSetAttribute(recur_kernel, cudaFuncAttributeMaxDynamicSharedMemorySize, RC_SMEM);

    // one-time prep: weight splits, bias sums, gather indices, state init
    prep_kernel<<<8192, 256>>>(gf, W_a, W_ih0, W_hh0, b_ih0, b_hh0,
                               W_ih1, W_hh1, b_ih1, b_hh1, captions);

    // node_proj = node_features @ W_c^T + b_c         [8192, 512]
    tgemm<<<dim3(NN_ / 128, H_ / 128), 256, TG_SMEM>>>(
        nf, H_, W_c, H_, node_proj, H_, b_c, H_, nullptr);

    // embpart = emb[captions] @ W_ih0[:, :512]^T + (b_ih0+b_hh0)   [1280, 2048]
    tgemm<<<dim3(T_ * B_ / 128, G4 / 128), 256, TG_SMEM>>>(
        emb, E_, W_ih0, 1024, embpart, G4, bs0, E_, gidx);

    // full recurrence: ONE persistent kernel, 20 steps, 6 barriers/step
    recur_kernel<<<NB, 256, RC_SMEM>>>(batch_idx, b_a);

    // logits = hist @ W_fc^T + b_fc  -> directly into out[b][t][v]
    tgemm<<<dim3(B_ * T_ / 128, V_ / 128), 256, TG_SMEM>>>(
        hist, H_, W_fc, H_, out, V_, b_fc, H_, nullptr);
}